// round 3
// baseline (speedup 1.0000x reference)
#include <cuda_runtime.h>
#include <math.h>

#define BB    1024   // batch
#define DD    1024   // embed dim
#define NE    128    // num experts / N
#define PT    28     // PT_DEPTH
#define KSEL  32     // k-1 (softmax'd top count)

// ---------------- scratch (device globals; no allocation allowed) ----------
__device__ float g_h[PT * DD];                     // silu(t*w1+b1) per step
__device__ __align__(16) float g_te[PT * DD];      // t_embed per unique step
__device__ float g_clean[PT * NE];                 // clean logits per step
__device__ float g_std[PT * NE];                   // noise std per step
__device__ float g_gates[BB * NE];                 // per-row gates
__device__ int   g_ts[BB];                         // decoded timesteps
__device__ int   g_step;                           // timestep[0]

// ---------------- 0) decode timestep buffer (int32 OR int64) ---------------
// If int64: first 1024 words = [t0,0,t1,0,...,t511,0] -> all odd words 0.
// If int32: odd words are random in [0,28); all-zero is impossible.
// Only reads within the smaller (4KB) valid region for detection; reads the
// 8KB region only after int64 is confirmed (buffer then is 8KB).
__global__ void k_decode(const int* __restrict__ raw) {
    __shared__ int is32;
    int tid = threadIdx.x;
    if (tid == 0) is32 = 0;
    __syncthreads();
    int w = raw[tid];                 // words 0..1023: valid either way
    if ((tid & 1) && w != 0) atomicOr(&is32, 1);
    __syncthreads();
    int v = is32 ? raw[tid] : raw[2 * tid];
    g_ts[tid] = v;
    if (tid == 0) g_step = v;
}

// ---------------- 1) h[s,i] = silu(s * w1[i] + b1[i]) ----------------------
__global__ void k_h(const float* __restrict__ w1, const float* __restrict__ b1) {
    int s = blockIdx.x, i = threadIdx.x;
    float x = (float)s * w1[i] + b1[i];
    g_h[s * DD + i] = x / (1.0f + expf(-x));       // silu
}

// ---------------- 2) t_embed[s,j] = dot(h[s,:], w2[j,:]) + b2[j] -----------
// One warp per output column j; 28 accumulators (one per step) per lane.
__global__ __launch_bounds__(128) void k_embed(const float* __restrict__ w2,
                                               const float* __restrict__ b2) {
    int lane = threadIdx.x & 31;
    int j = blockIdx.x * 4 + (threadIdx.x >> 5);
    const float* w2row = w2 + (size_t)j * DD;
    float acc[PT];
#pragma unroll
    for (int s = 0; s < PT; s++) acc[s] = 0.0f;
    for (int i = lane; i < DD; i += 32) {
        float wv = w2row[i];
#pragma unroll
        for (int s = 0; s < PT; s++) acc[s] += g_h[s * DD + i] * wv;
    }
#pragma unroll
    for (int s = 0; s < PT; s++) {
#pragma unroll
        for (int o = 16; o > 0; o >>= 1)
            acc[s] += __shfl_xor_sync(0xffffffffu, acc[s], o);
    }
    if (lane == 0) {
        float bb = b2[j];
#pragma unroll
        for (int s = 0; s < PT; s++) g_te[s * DD + j] = acc[s] + bb;
    }
}

// ---------------- 3) clean[s,n], std[s,n] ----------------------------------
// One warp per (s,n). clean = te . gate_w[n,:D] + step*gate_w[n,D] + gate_b[n]
// std = softplus(te . w_noise[:,n]) + 0.01
__global__ __launch_bounds__(32) void k_gate(const float* __restrict__ gate_w,
                                             const float* __restrict__ gate_b,
                                             const float* __restrict__ w_noise) {
    int s = blockIdx.x / NE;
    int n = blockIdx.x % NE;
    int lane = threadIdx.x;
    const float* gw = gate_w + (size_t)n * (DD + 1);
    const float* te = g_te + (size_t)s * DD;
    float ac = 0.0f, as = 0.0f;
    for (int j = lane; j < DD; j += 32) {
        float t = te[j];
        ac += t * gw[j];
        as += t * w_noise[(size_t)j * NE + n];
    }
#pragma unroll
    for (int o = 16; o > 0; o >>= 1) {
        ac += __shfl_xor_sync(0xffffffffu, ac, o);
        as += __shfl_xor_sync(0xffffffffu, as, o);
    }
    if (lane == 0) {
        g_clean[s * NE + n] = ac + (float)g_step * gw[DD] + gate_b[n];
        float sp = (as > 20.0f) ? as : log1pf(expf(as));   // softplus
        g_std[s * NE + n] = sp + 0.01f;                    // NOISE_EPS
    }
}

// ---------------- 4) per-row noisy top-32 softmax gates --------------------
// Exact-rank selection matches jax.lax.top_k's stable tie-break.
__global__ __launch_bounds__(NE) void k_topk(const float* __restrict__ noise) {
    __shared__ float sv[NE];
    __shared__ float red[NE];
    __shared__ float smax;
    int b = blockIdx.x, n = threadIdx.x;
    int s = g_ts[b];
    float v = g_clean[s * NE + n] + noise[(size_t)b * NE + n] * g_std[s * NE + n];
    sv[n] = v;
    __syncthreads();
    int rank = 0;
#pragma unroll 8
    for (int m = 0; m < NE; m++) {
        float u = sv[m];
        rank += (u > v) || (u == v && m < n);
    }
    if (rank == 0) smax = v;   // unique by tie-break
    __syncthreads();
    float e = (rank < KSEL) ? expf(v - smax) : 0.0f;
    red[n] = e;
    __syncthreads();
#pragma unroll
    for (int o = NE / 2; o > 0; o >>= 1) {
        if (n < o) red[n] += red[n + o];
        __syncthreads();
    }
    g_gates[b * NE + n] = e / red[0];
}

// ---------------- 5) out[b,n,:] = gates[b,n] * prompts[step,n,:] -----------
// One block per (b,n): gate is block-uniform; 256 threads x float4 = 4KB row.
__global__ __launch_bounds__(256) void k_out(const float* __restrict__ prompt,
                                             float* __restrict__ out) {
    int n = blockIdx.x, b = blockIdx.y, t = threadIdx.x;
    float g = g_gates[b * NE + n];
    const float4* p = (const float4*)(prompt + ((size_t)(g_step * NE + n)) * DD);
    float4 pv = p[t];
    float4 o;
    o.x = g * pv.x; o.y = g * pv.y; o.z = g * pv.z; o.w = g * pv.w;
    ((float4*)out)[((size_t)b * NE + n) * (DD / 4) + t] = o;
}

// ---------------- 6) t_embed output: gather dedup'd rows -------------------
__global__ __launch_bounds__(256) void k_temb(float* __restrict__ out) {
    int b = blockIdx.x, t = threadIdx.x;
    int s = g_ts[b];
    float4 v = ((const float4*)(g_te + (size_t)s * DD))[t];
    ((float4*)out)[(size_t)b * (DD / 4) + t] = v;
}

// ---------------- launch ---------------------------------------------------
extern "C" void kernel_launch(void* const* d_in, const int* in_sizes, int n_in,
                              void* d_out, int out_size) {
    const float* prompt  = (const float*)d_in[0];  // [28,128,1024]
    const float* w1      = (const float*)d_in[1];  // [1024,1]
    const float* b1      = (const float*)d_in[2];  // [1024]
    const float* w2      = (const float*)d_in[3];  // [1024,1024]
    const float* b2      = (const float*)d_in[4];  // [1024]
    const float* gate_w  = (const float*)d_in[5];  // [128,1025]
    const float* gate_b  = (const float*)d_in[6];  // [128]
    const float* w_noise = (const float*)d_in[7];  // [1024,128]
    const float* noise   = (const float*)d_in[8];  // [1024,128]
    const int*   tsraw   = (const int*)d_in[9];    // int32 or int64, detected
    float* out = (float*)d_out;

    k_decode<<<1, BB>>>(tsraw);
    k_h<<<PT, DD>>>(w1, b1);
    k_embed<<<DD / 4, 128>>>(w2, b2);
    k_gate<<<PT * NE, 32>>>(gate_w, gate_b, w_noise);
    k_topk<<<BB, NE>>>(noise);
    dim3 go(NE, BB);
    k_out<<<go, 256>>>(prompt, out);

    size_t main_sz = (size_t)BB * NE * DD;
    if ((size_t)out_size >= main_sz + (size_t)BB * DD)
        k_temb<<<BB, 256>>>(out + main_sz);
}